// round 2
// baseline (speedup 1.0000x reference)
#include <cuda_runtime.h>
#include <math.h>

// Fixed problem shapes (from reference): B=4, S=4096, D=512, H=64
#define BATCH 4
#define SEQ   4096
#define DMODEL 512
#define DHEAD  64
#define NROWS (BATCH*SEQ)          // 16384
#define BQ 64
#define BK 64
#define LDP 65                     // padded leading dim for smem tiles

// Scratch (no allocation allowed -> device globals). 4 MB each.
__device__ float g_Q[NROWS*DHEAD];
__device__ float g_K[NROWS*DHEAD];
__device__ float g_V[NROWS*DHEAD];
__device__ float g_O[NROWS*DHEAD];

// ---------------------------------------------------------------------------
// Kernel 1: QKV projection. 16 rows per block, 192 threads:
// threads [0,64) -> Q columns, [64,128) -> K, [128,192) -> V.
// ---------------------------------------------------------------------------
__global__ __launch_bounds__(192) void qkv_kernel(
    const float* __restrict__ x,
    const float* __restrict__ Wq, const float* __restrict__ bq,
    const float* __restrict__ Wk, const float* __restrict__ bk,
    const float* __restrict__ Wv, const float* __restrict__ bv)
{
    __shared__ float xs[16][DMODEL];
    const int row0 = blockIdx.x * 16;

    const float4* xg = (const float4*)(x + (size_t)row0 * DMODEL);
    float4* xsv = (float4*)&xs[0][0];
    for (int i = threadIdx.x; i < 16 * DMODEL / 4; i += 192) xsv[i] = xg[i];
    __syncthreads();

    const int g = threadIdx.x >> 6;     // 0=Q, 1=K, 2=V
    const int h = threadIdx.x & 63;
    const float* Wg = (g == 0) ? Wq : (g == 1) ? Wk : Wv;
    const float* bg = (g == 0) ? bq : (g == 1) ? bk : bv;

    float acc[16];
    const float bias = bg[h];
#pragma unroll
    for (int r = 0; r < 16; r++) acc[r] = bias;

#pragma unroll 4
    for (int d = 0; d < DMODEL; d++) {
        const float w = Wg[d * DHEAD + h];
#pragma unroll
        for (int r = 0; r < 16; r++) acc[r] = fmaf(xs[r][d], w, acc[r]);
    }

    float* dst = (g == 0) ? g_Q : (g == 1) ? g_K : g_V;
#pragma unroll
    for (int r = 0; r < 16; r++)
        dst[(size_t)(row0 + r) * DHEAD + h] = acc[r];
}

// ---------------------------------------------------------------------------
// Kernel 2: causal flash attention (fp32, online softmax).
// One block = (batch b, query tile of 64). 256 threads = 16x16 layout;
// each thread owns a 4(query) x 4(key/dim) fragment.
// scale = 1/sqrt(S) (reference divides by sqrt(seq_len), not sqrt(d_head)).
// ---------------------------------------------------------------------------
__global__ __launch_bounds__(256) void attn_kernel()
{
    extern __shared__ float sm[];
    float* Qs = sm;                   // [BQ][LDP]
    float* Ks = Qs + BQ * LDP;        // [BK][LDP]
    float* Vs = Ks + BK * LDP;        // [BK][LDP]
    float* Ps = Vs + BK * LDP;        // [BQ][LDP]

    const int tid = threadIdx.x;
    const int tx = tid & 15;
    const int ty = tid >> 4;
    const int b  = blockIdx.y;
    // reverse order: heaviest (largest qb) tiles launch first -> better tail
    const int qb = (SEQ / BQ - 1) - blockIdx.x;
    const int qbase = qb * BQ;
    const float scale = 0.015625f;    // 1/sqrt(4096) = 1/64

    const float* Qg = g_Q + (size_t)b * SEQ * DHEAD;
    const float* Kg = g_K + (size_t)b * SEQ * DHEAD;
    const float* Vg = g_V + (size_t)b * SEQ * DHEAD;

    // load Q tile (64 x 64)
    for (int i = tid; i < BQ * 16; i += 256) {
        const int r = i >> 4, c = (i & 15) << 2;
        float4 v = *(const float4*)&Qg[(size_t)(qbase + r) * DHEAD + c];
        Qs[r * LDP + c    ] = v.x;
        Qs[r * LDP + c + 1] = v.y;
        Qs[r * LDP + c + 2] = v.z;
        Qs[r * LDP + c + 3] = v.w;
    }

    float m[4], l[4], acc[4][4];
#pragma unroll
    for (int i = 0; i < 4; i++) {
        m[i] = -INFINITY; l[i] = 0.0f;
#pragma unroll
        for (int j = 0; j < 4; j++) acc[i][j] = 0.0f;
    }

    for (int kb = 0; kb <= qb; kb++) {
        const int kbase = kb * BK;

        // load K and V tiles
        for (int i = tid; i < BK * 16; i += 256) {
            const int r = i >> 4, c = (i & 15) << 2;
            float4 kv4 = *(const float4*)&Kg[(size_t)(kbase + r) * DHEAD + c];
            Ks[r * LDP + c] = kv4.x; Ks[r * LDP + c + 1] = kv4.y;
            Ks[r * LDP + c + 2] = kv4.z; Ks[r * LDP + c + 3] = kv4.w;
            float4 vv4 = *(const float4*)&Vg[(size_t)(kbase + r) * DHEAD + c];
            Vs[r * LDP + c] = vv4.x; Vs[r * LDP + c + 1] = vv4.y;
            Vs[r * LDP + c + 2] = vv4.z; Vs[r * LDP + c + 3] = vv4.w;
        }
        __syncthreads();

        // s = Q @ K^T fragment
        float s[4][4];
#pragma unroll
        for (int i = 0; i < 4; i++)
#pragma unroll
            for (int j = 0; j < 4; j++) s[i][j] = 0.0f;

#pragma unroll 4
        for (int d = 0; d < DHEAD; d++) {
            float qv[4], kv[4];
#pragma unroll
            for (int i = 0; i < 4; i++) qv[i] = Qs[(ty * 4 + i) * LDP + d];
#pragma unroll
            for (int j = 0; j < 4; j++) kv[j] = Ks[(tx * 4 + j) * LDP + d];
#pragma unroll
            for (int i = 0; i < 4; i++)
#pragma unroll
                for (int j = 0; j < 4; j++)
                    s[i][j] = fmaf(qv[i], kv[j], s[i][j]);
        }

#pragma unroll
        for (int i = 0; i < 4; i++)
#pragma unroll
            for (int j = 0; j < 4; j++) s[i][j] *= scale;

        if (kb == qb) {   // causal mask on the diagonal tile
#pragma unroll
            for (int i = 0; i < 4; i++)
#pragma unroll
                for (int j = 0; j < 4; j++)
                    if (kbase + tx * 4 + j > qbase + ty * 4 + i)
                        s[i][j] = -1e30f;
        }

        // online softmax: row max (across the 16 tx lanes), correction, sums
        float mnew[4], corr[4];
#pragma unroll
        for (int i = 0; i < 4; i++) {
            float rm = fmaxf(fmaxf(s[i][0], s[i][1]), fmaxf(s[i][2], s[i][3]));
            rm = fmaxf(rm, __shfl_xor_sync(0xffffffffu, rm, 1, 16));
            rm = fmaxf(rm, __shfl_xor_sync(0xffffffffu, rm, 2, 16));
            rm = fmaxf(rm, __shfl_xor_sync(0xffffffffu, rm, 4, 16));
            rm = fmaxf(rm, __shfl_xor_sync(0xffffffffu, rm, 8, 16));
            mnew[i] = fmaxf(m[i], rm);
            corr[i] = __expf(m[i] - mnew[i]);
            m[i] = mnew[i];
        }

#pragma unroll
        for (int i = 0; i < 4; i++) {
            float rs = 0.0f;
#pragma unroll
            for (int j = 0; j < 4; j++) {
                float p = __expf(s[i][j] - mnew[i]);
                s[i][j] = p;
                rs += p;
            }
            rs += __shfl_xor_sync(0xffffffffu, rs, 1, 16);
            rs += __shfl_xor_sync(0xffffffffu, rs, 2, 16);
            rs += __shfl_xor_sync(0xffffffffu, rs, 4, 16);
            rs += __shfl_xor_sync(0xffffffffu, rs, 8, 16);
            l[i] = l[i] * corr[i] + rs;
        }

#pragma unroll
        for (int i = 0; i < 4; i++)
#pragma unroll
            for (int j = 0; j < 4; j++) acc[i][j] *= corr[i];

        // stage P tile for the PV GEMM
#pragma unroll
        for (int i = 0; i < 4; i++)
#pragma unroll
            for (int j = 0; j < 4; j++)
                Ps[(ty * 4 + i) * LDP + tx * 4 + j] = s[i][j];
        __syncthreads();

        // acc += P @ V  (tx now indexes head dims)
#pragma unroll 4
        for (int kk = 0; kk < BK; kk++) {
            float pv[4], vv[4];
#pragma unroll
            for (int i = 0; i < 4; i++) pv[i] = Ps[(ty * 4 + i) * LDP + kk];
#pragma unroll
            for (int j = 0; j < 4; j++) vv[j] = Vs[kk * LDP + tx * 4 + j];
#pragma unroll
            for (int i = 0; i < 4; i++)
#pragma unroll
                for (int j = 0; j < 4; j++)
                    acc[i][j] = fmaf(pv[i], vv[j], acc[i][j]);
        }
        __syncthreads();
    }

    float* Og = g_O + (size_t)b * SEQ * DHEAD;
#pragma unroll
    for (int i = 0; i < 4; i++) {
        const float inv = 1.0f / l[i];
#pragma unroll
        for (int j = 0; j < 4; j++)
            Og[(size_t)(qbase + ty * 4 + i) * DHEAD + tx * 4 + j] = acc[i][j] * inv;
    }
}

// ---------------------------------------------------------------------------
// Kernel 3: output projection out = O @ Wo + bo. 16 rows/block, 512 threads
// (one output column each).
// ---------------------------------------------------------------------------
__global__ __launch_bounds__(512) void proj_kernel(
    const float* __restrict__ Wo, const float* __restrict__ bo,
    float* __restrict__ out)
{
    __shared__ float a[16][DHEAD];
    const int row0 = blockIdx.x * 16;

    const float4* og = (const float4*)(g_O + (size_t)row0 * DHEAD);
    float4* av = (float4*)&a[0][0];
    for (int i = threadIdx.x; i < 16 * DHEAD / 4; i += 512) av[i] = og[i];
    __syncthreads();

    const int c = threadIdx.x;   // 0..511
    float acc[16];
    const float bias = bo[c];
#pragma unroll
    for (int r = 0; r < 16; r++) acc[r] = bias;

#pragma unroll 8
    for (int h = 0; h < DHEAD; h++) {
        const float w = Wo[h * DMODEL + c];
#pragma unroll
        for (int r = 0; r < 16; r++) acc[r] = fmaf(a[r][h], w, acc[r]);
    }

#pragma unroll
    for (int r = 0; r < 16; r++)
        out[(size_t)(row0 + r) * DMODEL + c] = acc[r];
}

// ---------------------------------------------------------------------------
extern "C" void kernel_launch(void* const* d_in, const int* in_sizes, int n_in,
                              void* d_out, int out_size)
{
    const float* x  = (const float*)d_in[0];
    const float* Wq = (const float*)d_in[1];
    const float* bq = (const float*)d_in[2];
    const float* Wk = (const float*)d_in[3];
    const float* bk = (const float*)d_in[4];
    const float* Wv = (const float*)d_in[5];
    const float* bv = (const float*)d_in[6];
    const float* Wo = (const float*)d_in[7];
    const float* bo = (const float*)d_in[8];
    float* out = (float*)d_out;

    const int smem_attn = 4 * BQ * LDP * (int)sizeof(float);  // 66560 B
    cudaFuncSetAttribute(attn_kernel,
                         cudaFuncAttributeMaxDynamicSharedMemorySize, smem_attn);

    qkv_kernel<<<NROWS / 16, 192>>>(x, Wq, bq, Wk, bk, Wv, bv);
    attn_kernel<<<dim3(SEQ / BQ, BATCH), 256, smem_attn>>>();
    proj_kernel<<<NROWS / 16, 512>>>(Wo, bo, out);
}

// round 4
// speedup vs baseline: 1.4467x; 1.4467x over previous
#include <cuda_runtime.h>
#include <math.h>

// Fixed problem shapes: B=4, S=4096, D=512, H=64
#define BATCH 4
#define SEQ   4096
#define DMODEL 512
#define DHEAD  64
#define NROWS (BATCH*SEQ)          // 16384
#define BQ 64
#define BK 64

// Scratch (no allocation allowed -> device globals). 4 MB each.
__device__ float g_Q[NROWS*DHEAD];
__device__ float g_K[NROWS*DHEAD];
__device__ float g_V[NROWS*DHEAD];
__device__ float g_O[NROWS*DHEAD];

// ---------------------------------------------------------------------------
// Kernel 1: QKV projection as a tiled GEMM. Block = 64 rows x 64 cols (one of
// Q/K/V selected by blockIdx.y). 256 threads in 16x16 layout, 4x4 fragments.
// x chunk is staged transposed+swizzled so the inner loop is 2 LDS.128 per
// 16 FFMA. Swizzle: elem (d, c) of a transposed 64x64 tile lives at
// T[d*64 + (c ^ (d & 0x3C))]  -> conflict-free vector loads, <=2-way stores.
// ---------------------------------------------------------------------------
__global__ __launch_bounds__(256) void qkv_kernel(
    const float* __restrict__ x,
    const float* __restrict__ Wq, const float* __restrict__ bq,
    const float* __restrict__ Wk, const float* __restrict__ bk,
    const float* __restrict__ Wv, const float* __restrict__ bv)
{
    __shared__ float Xt[64*64];   // [d][row] swizzled
    __shared__ float Ws[64*64];   // [d][h]   row-major

    const int tid = threadIdx.x;
    const int tx = tid & 15, ty = tid >> 4;
    const int row0 = blockIdx.x * 64;
    const int g = blockIdx.y;
    const float* W  = (g == 0) ? Wq : (g == 1) ? Wk : Wv;
    const float* bb = (g == 0) ? bq : (g == 1) ? bk : bv;
    float* dst      = (g == 0) ? g_Q : (g == 1) ? g_K : g_V;

    float acc[4][4];
#pragma unroll
    for (int i = 0; i < 4; i++)
#pragma unroll
        for (int j = 0; j < 4; j++) acc[i][j] = 0.0f;

    for (int dc = 0; dc < DMODEL; dc += 64) {
        for (int i = tid; i < 64 * 16; i += 256) {
            const int r = i >> 4, c4 = (i & 15) << 2;
            float4 v = *(const float4*)&x[(size_t)(row0 + r) * DMODEL + dc + c4];
            const int rr = r ^ c4;                 // swz(d)=d&0x3C == c4 for d=c4..c4+3
            Xt[(c4 + 0) * 64 + rr] = v.x;
            Xt[(c4 + 1) * 64 + rr] = v.y;
            Xt[(c4 + 2) * 64 + rr] = v.z;
            Xt[(c4 + 3) * 64 + rr] = v.w;
            float4 w = *(const float4*)&W[(size_t)(dc + r) * DHEAD + c4];
            *(float4*)&Ws[r * 64 + c4] = w;
        }
        __syncthreads();

#pragma unroll
        for (int d4 = 0; d4 < 64; d4 += 4) {
            const float4* xp = (const float4*)&Xt[d4 * 64 + ((ty * 4) ^ d4)];
            const float4* wp = (const float4*)&Ws[d4 * 64 + tx * 4];
#pragma unroll
            for (int k = 0; k < 4; k++) {
                const float4 a4 = xp[k * 16];
                const float4 w4 = wp[k * 16];
                acc[0][0] = fmaf(a4.x, w4.x, acc[0][0]);
                acc[0][1] = fmaf(a4.x, w4.y, acc[0][1]);
                acc[0][2] = fmaf(a4.x, w4.z, acc[0][2]);
                acc[0][3] = fmaf(a4.x, w4.w, acc[0][3]);
                acc[1][0] = fmaf(a4.y, w4.x, acc[1][0]);
                acc[1][1] = fmaf(a4.y, w4.y, acc[1][1]);
                acc[1][2] = fmaf(a4.y, w4.z, acc[1][2]);
                acc[1][3] = fmaf(a4.y, w4.w, acc[1][3]);
                acc[2][0] = fmaf(a4.z, w4.x, acc[2][0]);
                acc[2][1] = fmaf(a4.z, w4.y, acc[2][1]);
                acc[2][2] = fmaf(a4.z, w4.z, acc[2][2]);
                acc[2][3] = fmaf(a4.z, w4.w, acc[2][3]);
                acc[3][0] = fmaf(a4.w, w4.x, acc[3][0]);
                acc[3][1] = fmaf(a4.w, w4.y, acc[3][1]);
                acc[3][2] = fmaf(a4.w, w4.z, acc[3][2]);
                acc[3][3] = fmaf(a4.w, w4.w, acc[3][3]);
            }
        }
        __syncthreads();
    }

    const float4 bias = *(const float4*)&bb[tx * 4];
#pragma unroll
    for (int i = 0; i < 4; i++) {
        float4 o;
        o.x = acc[i][0] + bias.x;
        o.y = acc[i][1] + bias.y;
        o.z = acc[i][2] + bias.z;
        o.w = acc[i][3] + bias.w;
        *(float4*)&dst[(size_t)(row0 + ty * 4 + i) * DHEAD + tx * 4] = o;
    }
}

// ---------------------------------------------------------------------------
// Kernel 2: causal flash attention (fp32, online softmax), vectorized.
// One block = one (batch, q-tile). 256 threads = 16x16, 4x4 fragments.
// Smem: Qt/Kt transposed+swizzled [d][seq], Vs row-major [seq][d],
// Pt transposed+swizzled [k][q]. Inner loops: 2 LDS.128 + 16 FFMA per step.
// Balanced schedule: with 256 blocks and ~296 resident slots, blocks b and
// b+148 share an SM; rank mapping makes singles heavy and pair sums ~const.
// scale = 1/sqrt(S) = 1/64 (reference divides by sqrt(seq_len)).
// ---------------------------------------------------------------------------
__global__ __launch_bounds__(256) void attn_kernel()
{
    extern __shared__ float sm[];
    float* Qt = sm;               // [64 d][64 q] swizzled
    float* Kt = Qt + 4096;        // [64 d][64 k] swizzled
    float* Vs = Kt + 4096;        // [64 k][64 d] row-major
    float* Pt = Vs + 4096;        // [64 k][64 q] swizzled

    const int tid = threadIdx.x;
    const int tx = tid & 15, ty = tid >> 4;

    // Balanced work-rank mapping (ranks sorted heavy->light):
    //   bid in [108,148): singles, ranks 0..39 (heaviest tiles)
    //   bid in [0,108):   ranks 40..147, paired with bid+148 -> ranks 255..148
    const int bid = blockIdx.x;
    const int rank = (bid < 108) ? (40 + bid) : (bid < 148) ? (bid - 108) : (403 - bid);
    const int qb = 63 - (rank >> 2);
    const int b  = rank & 3;
    const int qbase = qb * BQ;
    const float scale = 0.015625f;   // 1/sqrt(4096)

    const float* Qg = g_Q + (size_t)b * SEQ * DHEAD;
    const float* Kg = g_K + (size_t)b * SEQ * DHEAD;
    const float* Vg = g_V + (size_t)b * SEQ * DHEAD;

    // load Q tile transposed+swizzled
    for (int i = tid; i < 64 * 16; i += 256) {
        const int r = i >> 4, c4 = (i & 15) << 2;
        float4 v = *(const float4*)&Qg[(size_t)(qbase + r) * DHEAD + c4];
        const int rr = r ^ c4;
        Qt[(c4 + 0) * 64 + rr] = v.x;
        Qt[(c4 + 1) * 64 + rr] = v.y;
        Qt[(c4 + 2) * 64 + rr] = v.z;
        Qt[(c4 + 3) * 64 + rr] = v.w;
    }

    float m[4], l[4], acc[4][4];
#pragma unroll
    for (int i = 0; i < 4; i++) {
        m[i] = -INFINITY; l[i] = 0.0f;
#pragma unroll
        for (int j = 0; j < 4; j++) acc[i][j] = 0.0f;
    }

    for (int kb = 0; kb <= qb; kb++) {
        const int kbase = kb * BK;

        // load K (transposed+swizzled) and V (row-major) tiles
        for (int i = tid; i < 64 * 16; i += 256) {
            const int r = i >> 4, c4 = (i & 15) << 2;
            float4 k4 = *(const float4*)&Kg[(size_t)(kbase + r) * DHEAD + c4];
            const int rr = r ^ c4;
            Kt[(c4 + 0) * 64 + rr] = k4.x;
            Kt[(c4 + 1) * 64 + rr] = k4.y;
            Kt[(c4 + 2) * 64 + rr] = k4.z;
            Kt[(c4 + 3) * 64 + rr] = k4.w;
            float4 v4 = *(const float4*)&Vg[(size_t)(kbase + r) * DHEAD + c4];
            *(float4*)&Vs[r * 64 + c4] = v4;
        }
        __syncthreads();

        // s = Q @ K^T fragment
        float s[4][4];
#pragma unroll
        for (int i = 0; i < 4; i++)
#pragma unroll
            for (int j = 0; j < 4; j++) s[i][j] = 0.0f;

#pragma unroll
        for (int d4 = 0; d4 < 64; d4 += 4) {
            const float4* qp = (const float4*)&Qt[d4 * 64 + ((ty * 4) ^ d4)];
            const float4* kp = (const float4*)&Kt[d4 * 64 + ((tx * 4) ^ d4)];
#pragma unroll
            for (int k = 0; k < 4; k++) {
                const float4 q4 = qp[k * 16];
                const float4 k4 = kp[k * 16];
                s[0][0] = fmaf(q4.x, k4.x, s[0][0]);
                s[0][1] = fmaf(q4.x, k4.y, s[0][1]);
                s[0][2] = fmaf(q4.x, k4.z, s[0][2]);
                s[0][3] = fmaf(q4.x, k4.w, s[0][3]);
                s[1][0] = fmaf(q4.y, k4.x, s[1][0]);
                s[1][1] = fmaf(q4.y, k4.y, s[1][1]);
                s[1][2] = fmaf(q4.y, k4.z, s[1][2]);
                s[1][3] = fmaf(q4.y, k4.w, s[1][3]);
                s[2][0] = fmaf(q4.z, k4.x, s[2][0]);
                s[2][1] = fmaf(q4.z, k4.y, s[2][1]);
                s[2][2] = fmaf(q4.z, k4.z, s[2][2]);
                s[2][3] = fmaf(q4.z, k4.w, s[2][3]);
                s[3][0] = fmaf(q4.w, k4.x, s[3][0]);
                s[3][1] = fmaf(q4.w, k4.y, s[3][1]);
                s[3][2] = fmaf(q4.w, k4.z, s[3][2]);
                s[3][3] = fmaf(q4.w, k4.w, s[3][3]);
            }
        }

#pragma unroll
        for (int i = 0; i < 4; i++)
#pragma unroll
            for (int j = 0; j < 4; j++) s[i][j] *= scale;

        if (kb == qb) {   // causal mask on diagonal tile
#pragma unroll
            for (int i = 0; i < 4; i++)
#pragma unroll
                for (int j = 0; j < 4; j++)
                    if (tx * 4 + j > ty * 4 + i) s[i][j] = -1e30f;
        }

        // online softmax (row reductions across the 16 tx lanes)
        float mnew[4], corr[4];
#pragma unroll
        for (int i = 0; i < 4; i++) {
            float rm = fmaxf(fmaxf(s[i][0], s[i][1]), fmaxf(s[i][2], s[i][3]));
            rm = fmaxf(rm, __shfl_xor_sync(0xffffffffu, rm, 1, 16));
            rm = fmaxf(rm, __shfl_xor_sync(0xffffffffu, rm, 2, 16));
            rm = fmaxf(rm, __shfl_xor_sync(0xffffffffu, rm, 4, 16));
            rm = fmaxf(rm, __shfl_xor_sync(0xffffffffu, rm, 8, 16));
            mnew[i] = fmaxf(m[i], rm);
            corr[i] = __expf(m[i] - mnew[i]);
            m[i] = mnew[i];
        }

#pragma unroll
        for (int i = 0; i < 4; i++) {
            float rs = 0.0f;
#pragma unroll
            for (int j = 0; j < 4; j++) {
                const float p = __expf(s[i][j] - mnew[i]);
                s[i][j] = p;
                rs += p;
            }
            rs += __shfl_xor_sync(0xffffffffu, rs, 1, 16);
            rs += __shfl_xor_sync(0xffffffffu, rs, 2, 16);
            rs += __shfl_xor_sync(0xffffffffu, rs, 4, 16);
            rs += __shfl_xor_sync(0xffffffffu, rs, 8, 16);
            l[i] = l[i] * corr[i] + rs;
        }

#pragma unroll
        for (int i = 0; i < 4; i++)
#pragma unroll
            for (int j = 0; j < 4; j++) acc[i][j] *= corr[i];

        // stage P transposed+swizzled: Pt[k][q], swz(k)=k&0x3C == tx*4 here
        {
            const int swp = tx * 4;
#pragma unroll
            for (int i = 0; i < 4; i++)
#pragma unroll
                for (int j = 0; j < 4; j++)
                    Pt[(tx * 4 + j) * 64 + ((ty * 4 + i) ^ swp)] = s[i][j];
        }
        __syncthreads();

        // acc += P @ V
#pragma unroll
        for (int k4i = 0; k4i < 64; k4i += 4) {
            const float4* pp = (const float4*)&Pt[k4i * 64 + ((ty * 4) ^ k4i)];
            const float4* vp = (const float4*)&Vs[k4i * 64 + tx * 4];
#pragma unroll
            for (int k = 0; k < 4; k++) {
                const float4 p4 = pp[k * 16];
                const float4 v4 = vp[k * 16];
                acc[0][0] = fmaf(p4.x, v4.x, acc[0][0]);
                acc[0][1] = fmaf(p4.x, v4.y, acc[0][1]);
                acc[0][2] = fmaf(p4.x, v4.z, acc[0][2]);
                acc[0][3] = fmaf(p4.x, v4.w, acc[0][3]);
                acc[1][0] = fmaf(p4.y, v4.x, acc[1][0]);
                acc[1][1] = fmaf(p4.y, v4.y, acc[1][1]);
                acc[1][2] = fmaf(p4.y, v4.z, acc[1][2]);
                acc[1][3] = fmaf(p4.y, v4.w, acc[1][3]);
                acc[2][0] = fmaf(p4.z, v4.x, acc[2][0]);
                acc[2][1] = fmaf(p4.z, v4.y, acc[2][1]);
                acc[2][2] = fmaf(p4.z, v4.z, acc[2][2]);
                acc[2][3] = fmaf(p4.z, v4.w, acc[2][3]);
                acc[3][0] = fmaf(p4.w, v4.x, acc[3][0]);
                acc[3][1] = fmaf(p4.w, v4.y, acc[3][1]);
                acc[3][2] = fmaf(p4.w, v4.z, acc[3][2]);
                acc[3][3] = fmaf(p4.w, v4.w, acc[3][3]);
            }
        }
        __syncthreads();
    }

    float* Og = g_O + (size_t)b * SEQ * DHEAD;
#pragma unroll
    for (int i = 0; i < 4; i++) {
        const float inv = 1.0f / l[i];
        float4 o;
        o.x = acc[i][0] * inv;
        o.y = acc[i][1] * inv;
        o.z = acc[i][2] * inv;
        o.w = acc[i][3] * inv;
        *(float4*)&Og[(size_t)(qbase + ty * 4 + i) * DHEAD + tx * 4] = o;
    }
}

// ---------------------------------------------------------------------------
// Kernel 3: output projection out = O @ Wo + bo, tiled GEMM (K-dim = 64).
// Block = 64 rows x 64 cols, 256 threads, 4x4 fragments.
// ---------------------------------------------------------------------------
__global__ __launch_bounds__(256) void proj_kernel(
    const float* __restrict__ Wo, const float* __restrict__ bo,
    float* __restrict__ out)
{
    __shared__ float At[64*64];   // [h][row] swizzled
    __shared__ float Ws[64*64];   // [h][c]   row-major

    const int tid = threadIdx.x;
    const int tx = tid & 15, ty = tid >> 4;
    const int row0 = blockIdx.x * 64;
    const int c0 = blockIdx.y * 64;

    for (int i = tid; i < 64 * 16; i += 256) {
        const int r = i >> 4, c4 = (i & 15) << 2;
        float4 a4 = *(const float4*)&g_O[(size_t)(row0 + r) * DHEAD + c4];
        const int rr = r ^ c4;
        At[(c4 + 0) * 64 + rr] = a4.x;
        At[(c4 + 1) * 64 + rr] = a4.y;
        At[(c4 + 2) * 64 + rr] = a4.z;
        At[(c4 + 3) * 64 + rr] = a4.w;
        float4 w4 = *(const float4*)&Wo[(size_t)r * DMODEL + c0 + c4];
        *(float4*)&Ws[r * 64 + c4] = w4;
    }
    __syncthreads();

    float acc[4][4];
#pragma unroll
    for (int i = 0; i < 4; i++)
#pragma unroll
        for (int j = 0; j < 4; j++) acc[i][j] = 0.0f;

#pragma unroll
    for (int h4 = 0; h4 < 64; h4 += 4) {
        const float4* ap = (const float4*)&At[h4 * 64 + ((ty * 4) ^ h4)];
        const float4* wp = (const float4*)&Ws[h4 * 64 + tx * 4];
#pragma unroll
        for (int k = 0; k < 4; k++) {
            const float4 a4 = ap[k * 16];
            const float4 w4 = wp[k * 16];
            acc[0][0] = fmaf(a4.x, w4.x, acc[0][0]);
            acc[0][1] = fmaf(a4.x, w4.y, acc[0][1]);
            acc[0][2] = fmaf(a4.x, w4.z, acc[0][2]);
            acc[0][3] = fmaf(a4.x, w4.w, acc[0][3]);
            acc[1][0] = fmaf(a4.y, w4.x, acc[1][0]);
            acc[1][1] = fmaf(a4.y, w4.y, acc[1][1]);
            acc[1][2] = fmaf(a4.y, w4.z, acc[1][2]);
            acc[1][3] = fmaf(a4.y, w4.w, acc[1][3]);
            acc[2][0] = fmaf(a4.z, w4.x, acc[2][0]);
            acc[2][1] = fmaf(a4.z, w4.y, acc[2][1]);
            acc[2][2] = fmaf(a4.z, w4.z, acc[2][2]);
            acc[2][3] = fmaf(a4.z, w4.w, acc[2][3]);
            acc[3][0] = fmaf(a4.w, w4.x, acc[3][0]);
            acc[3][1] = fmaf(a4.w, w4.y, acc[3][1]);
            acc[3][2] = fmaf(a4.w, w4.z, acc[3][2]);
            acc[3][3] = fmaf(a4.w, w4.w, acc[3][3]);
        }
    }

    const float4 bias = *(const float4*)&bo[c0 + tx * 4];
#pragma unroll
    for (int i = 0; i < 4; i++) {
        float4 o;
        o.x = acc[i][0] + bias.x;
        o.y = acc[i][1] + bias.y;
        o.z = acc[i][2] + bias.z;
        o.w = acc[i][3] + bias.w;
        *(float4*)&out[(size_t)(row0 + ty * 4 + i) * DMODEL + c0 + tx * 4] = o;
    }
}

// ---------------------------------------------------------------------------
extern "C" void kernel_launch(void* const* d_in, const int* in_sizes, int n_in,
                              void* d_out, int out_size)
{
    const float* x  = (const float*)d_in[0];
    const float* Wq = (const float*)d_in[1];
    const float* bq = (const float*)d_in[2];
    const float* Wk = (const float*)d_in[3];
    const float* bk = (const float*)d_in[4];
    const float* Wv = (const float*)d_in[5];
    const float* bv = (const float*)d_in[6];
    const float* Wo = (const float*)d_in[7];
    const float* bo = (const float*)d_in[8];
    float* out = (float*)d_out;

    const int smem_attn = 4 * 64 * 64 * (int)sizeof(float);  // 65536 B
    cudaFuncSetAttribute(attn_kernel,
                         cudaFuncAttributeMaxDynamicSharedMemorySize, smem_attn);

    qkv_kernel<<<dim3(NROWS / 64, 3), 256>>>(x, Wq, bq, Wk, bk, Wv, bv);
    attn_kernel<<<(SEQ / BQ) * BATCH, 256, smem_attn>>>();
    proj_kernel<<<dim3(NROWS / 64, DMODEL / 64), 256>>>(Wo, bo, out);
}

// round 7
// speedup vs baseline: 2.9529x; 2.0411x over previous
#include <cuda_runtime.h>
#include <cuda_fp16.h>
#include <math.h>
#include <cstdint>

// Fixed problem shapes: B=4, S=4096, D=512, H=64
#define BATCH 4
#define SEQ   4096
#define DMODEL 512
#define DHEAD  64
#define NROWS (BATCH*SEQ)          // 16384

// Scratch (device globals; no allocations allowed).
__device__ __half g_Qh[NROWS*DHEAD];   // fp16 Q row-major [row][h]
__device__ __half g_Kh[NROWS*DHEAD];   // fp16 K row-major
__device__ __half g_Vh[NROWS*DHEAD];   // fp16 V row-major
__device__ float  g_O[NROWS*DHEAD];    // fp32 attention output

// ===========================================================================
// Warp-level MMA helpers (portable PTX: works on compute_103 virtual arch)
// ===========================================================================
__device__ __forceinline__ uint32_t smem_u32(const void* p) {
    uint32_t a;
    asm("{ .reg .u64 t; cvta.to.shared.u64 t, %1; cvt.u32.u64 %0, t; }" : "=r"(a) : "l"(p));
    return a;
}
// D(16x8,f32) += A(16x16,f16) * B(16x8,f16): row.col
__device__ __forceinline__ void mma16816(float* d, const uint32_t* a, const uint32_t* b) {
    asm volatile(
        "mma.sync.aligned.m16n8k16.row.col.f32.f16.f16.f32 "
        "{%0,%1,%2,%3}, {%4,%5,%6,%7}, {%8,%9}, {%0,%1,%2,%3};"
        : "+f"(d[0]), "+f"(d[1]), "+f"(d[2]), "+f"(d[3])
        : "r"(a[0]), "r"(a[1]), "r"(a[2]), "r"(a[3]), "r"(b[0]), "r"(b[1]));
}
__device__ __forceinline__ void ldsm_x4(uint32_t* r, uint32_t addr) {
    asm volatile("ldmatrix.sync.aligned.m8n8.x4.shared.b16 {%0,%1,%2,%3}, [%4];"
        : "=r"(r[0]), "=r"(r[1]), "=r"(r[2]), "=r"(r[3]) : "r"(addr));
}
__device__ __forceinline__ void ldsm_x2(uint32_t* r, uint32_t addr) {
    asm volatile("ldmatrix.sync.aligned.m8n8.x2.shared.b16 {%0,%1}, [%2];"
        : "=r"(r[0]), "=r"(r[1]) : "r"(addr));
}
__device__ __forceinline__ void ldsm_x2t(uint32_t* r, uint32_t addr) {
    asm volatile("ldmatrix.sync.aligned.m8n8.x2.trans.shared.b16 {%0,%1}, [%2];"
        : "=r"(r[0]), "=r"(r[1]) : "r"(addr));
}
__device__ __forceinline__ float fast_exp2(float x) {
    float r;
    asm("ex2.approx.f32 %0, %1;" : "=f"(r) : "f"(x));
    return r;
}

// ===========================================================================
// Kernel 1: QKV projection (fp32 SIMT GEMM) with fp16 epilogue (all row-major).
// ===========================================================================
__global__ __launch_bounds__(256) void qkv_kernel(
    const float* __restrict__ x,
    const float* __restrict__ Wq, const float* __restrict__ bq,
    const float* __restrict__ Wk, const float* __restrict__ bk,
    const float* __restrict__ Wv, const float* __restrict__ bv)
{
    __shared__ float Xt[64*64];   // [d][row] swizzled
    __shared__ float Ws[64*64];   // [d][h]   row-major

    const int tid = threadIdx.x;
    const int tx = tid & 15, ty = tid >> 4;
    const int row0 = blockIdx.x * 64;
    const int g = blockIdx.y;
    const float* W  = (g == 0) ? Wq : (g == 1) ? Wk : Wv;
    const float* bb = (g == 0) ? bq : (g == 1) ? bk : bv;
    __half* dsth    = (g == 0) ? g_Qh : (g == 1) ? g_Kh : g_Vh;

    float acc[4][4];
#pragma unroll
    for (int i = 0; i < 4; i++)
#pragma unroll
        for (int j = 0; j < 4; j++) acc[i][j] = 0.0f;

    for (int dc = 0; dc < DMODEL; dc += 64) {
        for (int i = tid; i < 64 * 16; i += 256) {
            const int r = i >> 4, c4 = (i & 15) << 2;
            float4 v = *(const float4*)&x[(size_t)(row0 + r) * DMODEL + dc + c4];
            const int rr = r ^ c4;
            Xt[(c4 + 0) * 64 + rr] = v.x;
            Xt[(c4 + 1) * 64 + rr] = v.y;
            Xt[(c4 + 2) * 64 + rr] = v.z;
            Xt[(c4 + 3) * 64 + rr] = v.w;
            float4 w = *(const float4*)&W[(size_t)(dc + r) * DHEAD + c4];
            *(float4*)&Ws[r * 64 + c4] = w;
        }
        __syncthreads();

#pragma unroll
        for (int d4 = 0; d4 < 64; d4 += 4) {
            const float4* xp = (const float4*)&Xt[d4 * 64 + ((ty * 4) ^ d4)];
            const float4* wp = (const float4*)&Ws[d4 * 64 + tx * 4];
#pragma unroll
            for (int k = 0; k < 4; k++) {
                const float4 a4 = xp[k * 16];
                const float4 w4 = wp[k * 16];
                acc[0][0] = fmaf(a4.x, w4.x, acc[0][0]);
                acc[0][1] = fmaf(a4.x, w4.y, acc[0][1]);
                acc[0][2] = fmaf(a4.x, w4.z, acc[0][2]);
                acc[0][3] = fmaf(a4.x, w4.w, acc[0][3]);
                acc[1][0] = fmaf(a4.y, w4.x, acc[1][0]);
                acc[1][1] = fmaf(a4.y, w4.y, acc[1][1]);
                acc[1][2] = fmaf(a4.y, w4.z, acc[1][2]);
                acc[1][3] = fmaf(a4.y, w4.w, acc[1][3]);
                acc[2][0] = fmaf(a4.z, w4.x, acc[2][0]);
                acc[2][1] = fmaf(a4.z, w4.y, acc[2][1]);
                acc[2][2] = fmaf(a4.z, w4.z, acc[2][2]);
                acc[2][3] = fmaf(a4.z, w4.w, acc[2][3]);
                acc[3][0] = fmaf(a4.w, w4.x, acc[3][0]);
                acc[3][1] = fmaf(a4.w, w4.y, acc[3][1]);
                acc[3][2] = fmaf(a4.w, w4.z, acc[3][2]);
                acc[3][3] = fmaf(a4.w, w4.w, acc[3][3]);
            }
        }
        __syncthreads();
    }

    const float4 bias = *(const float4*)&bb[tx * 4];
#pragma unroll
    for (int i = 0; i < 4; i++) {
        const size_t rg = row0 + ty * 4 + i;
        __half2 p0 = __floats2half2_rn(acc[i][0] + bias.x, acc[i][1] + bias.y);
        __half2 p1 = __floats2half2_rn(acc[i][2] + bias.z, acc[i][3] + bias.w);
        *(__half2*)&dsth[rg * DHEAD + tx * 4]     = p0;
        *(__half2*)&dsth[rg * DHEAD + tx * 4 + 2] = p1;
    }
}

// ===========================================================================
// Kernel 2: fp16 mma.sync flash attention (FA2-style).
// One block = (q-tile of 128, batch). 8 warps; warp w owns q-rows [16w,16w+16).
// Smem tiles SW128-swizzled: half chunk (r, c8) at r*64 + ((c8 ^ (r&7))*8).
// Per 64-key tile: S = Q*K^T (32 mma/warp), scale+mask+online softmax in
// registers, P repacked to A-frags, O += P*V (32 mma/warp, ldmatrix.trans V).
// scale = 1/sqrt(4096) folded into exp2 constant.
// ===========================================================================
__global__ __launch_bounds__(256, 1) void attn_kernel()
{
    __shared__ __align__(1024) __half Qs[128*64];
    __shared__ __align__(1024) __half Ks[64*64];
    __shared__ __align__(1024) __half Vs[64*64];

    const int tid  = threadIdx.x;
    const int lane = tid & 31;
    const int warp = tid >> 5;
    const int qt = blockIdx.x;           // 0..31
    const int b  = blockIdx.y;           // 0..3
    const int qbase = qt * 128;

    // load Q tile (128 x 64 fp16 = 1024 16B-chunks)
    const __half* Qg = g_Qh + ((size_t)b * SEQ + qbase) * DHEAD;
    for (int i = tid; i < 1024; i += 256) {
        const int r = i >> 3, c = i & 7;
        uint4 v = *(const uint4*)&Qg[(size_t)r * 64 + c * 8];
        *(uint4*)&Qs[r * 64 + ((c ^ (r & 7)) * 8)] = v;
    }
    __syncthreads();

    const uint32_t qs_b = smem_u32(Qs);
    const uint32_t ks_b = smem_u32(Ks);
    const uint32_t vs_b = smem_u32(Vs);

    // A-fragments of Q (persist across k-tiles): 4 k-frags (d = 16*kk)
    const int q0 = warp * 16;
    uint32_t qa[4][4];
    {
        const int rowl = q0 + (lane & 15);
        const int hb = lane >> 4;                  // 0: d-lo, 1: d-hi 8
#pragma unroll
        for (int kk = 0; kk < 4; kk++) {
            uint32_t addr = qs_b + rowl * 128 + (((2 * kk + hb) ^ (rowl & 7)) * 16);
            ldsm_x4(qa[kk], addr);
        }
    }

    // per-lane ldmatrix address offsets
    const int rl  = lane & 7;
    const int hb8 = (lane >> 3) & 1;
    uint32_t koff[4];
#pragma unroll
    for (int kk = 0; kk < 4; kk++)
        koff[kk] = (uint32_t)(rl * 128 + (((2 * kk + hb8) ^ rl) * 16));
    const uint32_t voff = (uint32_t)((lane & 15) * 128);

    const int row0 = qbase + q0 + (lane >> 2);     // this lane's first q-row
    const float C = 0.015625f * 1.44269504088896f; // (1/sqrt(4096)) * log2(e)

    float m0 = -1e30f, m1 = -1e30f, l0 = 0.0f, l1 = 0.0f;
    float o[8][4];
#pragma unroll
    for (int j = 0; j < 8; j++)
#pragma unroll
        for (int k = 0; k < 4; k++) o[j][k] = 0.0f;

    const int nkb = 2 * qt + 2;

    for (int kb = 0; kb < nkb; kb++) {
        // ---- load K, V tiles (64 x 64 fp16 each) ----
        const __half* Kg = g_Kh + ((size_t)b * SEQ + kb * 64) * DHEAD;
        const __half* Vg = g_Vh + ((size_t)b * SEQ + kb * 64) * DHEAD;
        for (int i = tid; i < 512; i += 256) {
            const int r = i >> 3, c = i & 7;
            uint4 kv = *(const uint4*)&Kg[(size_t)r * 64 + c * 8];
            *(uint4*)&Ks[r * 64 + ((c ^ (r & 7)) * 8)] = kv;
            uint4 vv = *(const uint4*)&Vg[(size_t)r * 64 + c * 8];
            *(uint4*)&Vs[r * 64 + ((c ^ (r & 7)) * 8)] = vv;
        }
        __syncthreads();

        // ---- S = Q * K^T : 8 n-frags (8 keys each) x 4 k-frags ----
        float s[8][4];
#pragma unroll
        for (int j = 0; j < 8; j++)
#pragma unroll
            for (int k = 0; k < 4; k++) s[j][k] = 0.0f;

#pragma unroll
        for (int j = 0; j < 8; j++) {
#pragma unroll
            for (int kk = 0; kk < 4; kk++) {
                uint32_t bf[2];
                ldsm_x2(bf, ks_b + (uint32_t)(j * 1024) + koff[kk]);
                mma16816(s[j], qa[kk], bf);
            }
        }

        // ---- scale (+ causal mask on diagonal tiles) ----
#pragma unroll
        for (int j = 0; j < 8; j++)
#pragma unroll
            for (int k = 0; k < 4; k++) s[j][k] *= C;

        if (kb * 64 + 63 > qbase + q0) {
#pragma unroll
            for (int j = 0; j < 8; j++) {
                const int kc = kb * 64 + 8 * j + 2 * (lane & 3);
                if (kc     > row0)     s[j][0] = -1e30f;
                if (kc + 1 > row0)     s[j][1] = -1e30f;
                if (kc     > row0 + 8) s[j][2] = -1e30f;
                if (kc + 1 > row0 + 8) s[j][3] = -1e30f;
            }
        }

        // ---- online softmax (rows row0, row0+8) ----
        float mx0 = -1e30f, mx1 = -1e30f;
#pragma unroll
        for (int j = 0; j < 8; j++) {
            mx0 = fmaxf(mx0, fmaxf(s[j][0], s[j][1]));
            mx1 = fmaxf(mx1, fmaxf(s[j][2], s[j][3]));
        }
        mx0 = fmaxf(mx0, __shfl_xor_sync(0xffffffffu, mx0, 1, 4));
        mx0 = fmaxf(mx0, __shfl_xor_sync(0xffffffffu, mx0, 2, 4));
        mx1 = fmaxf(mx1, __shfl_xor_sync(0xffffffffu, mx1, 1, 4));
        mx1 = fmaxf(mx1, __shfl_xor_sync(0xffffffffu, mx1, 2, 4));

        const float mn0 = fmaxf(m0, mx0);
        const float mn1 = fmaxf(m1, mx1);
        const float c0 = fast_exp2(m0 - mn0);
        const float c1 = fast_exp2(m1 - mn1);
        m0 = mn0; m1 = mn1;

        uint32_t pa[4][4];
        float sum0 = 0.0f, sum1 = 0.0f;
#pragma unroll
        for (int j = 0; j < 8; j++) {
            const float p0 = fast_exp2(s[j][0] - mn0);
            const float p1 = fast_exp2(s[j][1] - mn0);
            const float p2 = fast_exp2(s[j][2] - mn1);
            const float p3 = fast_exp2(s[j][3] - mn1);
            sum0 += p0 + p1;
            sum1 += p2 + p3;
            const __half2 h01 = __floats2half2_rn(p0, p1);
            const __half2 h23 = __floats2half2_rn(p2, p3);
            const int kk = j >> 1, hi = (j & 1) << 1;     // 0 or 2
            pa[kk][hi]     = *(const uint32_t*)&h01;
            pa[kk][hi + 1] = *(const uint32_t*)&h23;
        }
        sum0 += __shfl_xor_sync(0xffffffffu, sum0, 1, 4);
        sum0 += __shfl_xor_sync(0xffffffffu, sum0, 2, 4);
        sum1 += __shfl_xor_sync(0xffffffffu, sum1, 1, 4);
        sum1 += __shfl_xor_sync(0xffffffffu, sum1, 2, 4);
        l0 = l0 * c0 + sum0;
        l1 = l1 * c1 + sum1;

#pragma unroll
        for (int j = 0; j < 8; j++) {
            o[j][0] *= c0; o[j][1] *= c0;
            o[j][2] *= c1; o[j][3] *= c1;
        }

        // ---- O += P * V : A = pa (16x16 keys), B = V^T via ldmatrix.trans ----
#pragma unroll
        for (int kk = 0; kk < 4; kk++) {
#pragma unroll
            for (int j = 0; j < 8; j++) {
                uint32_t vb[2];
                ldsm_x2t(vb, vs_b + (uint32_t)(kk * 2048) + voff + (uint32_t)(((j ^ rl) * 16)));
                mma16816(o[j], pa[kk], vb);
            }
        }
        __syncthreads();   // tiles safe to overwrite next iter
    }

    // ---- epilogue: write fp32 O rows ----
    const float inv0 = 1.0f / l0;
    const float inv1 = 1.0f / l1;
    float* O0 = g_O + ((size_t)b * SEQ + row0) * DHEAD;
    float* O1 = O0 + 8 * DHEAD;
    const int cbase = 2 * (lane & 3);
#pragma unroll
    for (int j = 0; j < 8; j++) {
        float2 w0 = make_float2(o[j][0] * inv0, o[j][1] * inv0);
        float2 w1 = make_float2(o[j][2] * inv1, o[j][3] * inv1);
        *(float2*)&O0[8 * j + cbase] = w0;
        *(float2*)&O1[8 * j + cbase] = w1;
    }
}

// ===========================================================================
// Kernel 3: output projection out = O @ Wo + bo (fp32 SIMT, unchanged).
// ===========================================================================
__global__ __launch_bounds__(256) void proj_kernel(
    const float* __restrict__ Wo, const float* __restrict__ bo,
    float* __restrict__ out)
{
    __shared__ float At[64*64];   // [h][row] swizzled
    __shared__ float Ws[64*64];   // [h][c]   row-major

    const int tid = threadIdx.x;
    const int tx = tid & 15, ty = tid >> 4;
    const int row0 = blockIdx.x * 64;
    const int c0 = blockIdx.y * 64;

    for (int i = tid; i < 64 * 16; i += 256) {
        const int r = i >> 4, c4 = (i & 15) << 2;
        float4 a4 = *(const float4*)&g_O[(size_t)(row0 + r) * DHEAD + c4];
        const int rr = r ^ c4;
        At[(c4 + 0) * 64 + rr] = a4.x;
        At[(c4 + 1) * 64 + rr] = a4.y;
        At[(c4 + 2) * 64 + rr] = a4.z;
        At[(c4 + 3) * 64 + rr] = a4.w;
        float4 w4 = *(const float4*)&Wo[(size_t)r * DMODEL + c0 + c4];
        *(float4*)&Ws[r * 64 + c4] = w4;
    }
    __syncthreads();

    float acc[4][4];
#pragma unroll
    for (int i = 0; i < 4; i++)
#pragma unroll
        for (int j = 0; j < 4; j++) acc[i][j] = 0.0f;

#pragma unroll
    for (int h4 = 0; h4 < 64; h4 += 4) {
        const float4* ap = (const float4*)&At[h4 * 64 + ((ty * 4) ^ h4)];
        const float4* wp = (const float4*)&Ws[h4 * 64 + tx * 4];
#pragma unroll
        for (int k = 0; k < 4; k++) {
            const float4 a4 = ap[k * 16];
            const float4 w4 = wp[k * 16];
            acc[0][0] = fmaf(a4.x, w4.x, acc[0][0]);
            acc[0][1] = fmaf(a4.x, w4.y, acc[0][1]);
            acc[0][2] = fmaf(a4.x, w4.z, acc[0][2]);
            acc[0][3] = fmaf(a4.x, w4.w, acc[0][3]);
            acc[1][0] = fmaf(a4.y, w4.x, acc[1][0]);
            acc[1][1] = fmaf(a4.y, w4.y, acc[1][1]);
            acc[1][2] = fmaf(a4.y, w4.z, acc[1][2]);
            acc[1][3] = fmaf(a4.y, w4.w, acc[1][3]);
            acc[2][0] = fmaf(a4.z, w4.x, acc[2][0]);
            acc[2][1] = fmaf(a4.z, w4.y, acc[2][1]);
            acc[2][2] = fmaf(a4.z, w4.z, acc[2][2]);
            acc[2][3] = fmaf(a4.z, w4.w, acc[2][3]);
            acc[3][0] = fmaf(a4.w, w4.x, acc[3][0]);
            acc[3][1] = fmaf(a4.w, w4.y, acc[3][1]);
            acc[3][2] = fmaf(a4.w, w4.z, acc[3][2]);
            acc[3][3] = fmaf(a4.w, w4.w, acc[3][3]);
        }
    }

    const float4 bias = *(const float4*)&bo[c0 + tx * 4];
#pragma unroll
    for (int i = 0; i < 4; i++) {
        float4 o;
        o.x = acc[i][0] + bias.x;
        o.y = acc[i][1] + bias.y;
        o.z = acc[i][2] + bias.z;
        o.w = acc[i][3] + bias.w;
        *(float4*)&out[(size_t)(row0 + ty * 4 + i) * DMODEL + c0 + tx * 4] = o;
    }
}

// ---------------------------------------------------------------------------
extern "C" void kernel_launch(void* const* d_in, const int* in_sizes, int n_in,
                              void* d_out, int out_size)
{
    const float* x  = (const float*)d_in[0];
    const float* Wq = (const float*)d_in[1];
    const float* bq = (const float*)d_in[2];
    const float* Wk = (const float*)d_in[3];
    const float* bk = (const float*)d_in[4];
    const float* Wv = (const float*)d_in[5];
    const float* bv = (const float*)d_in[6];
    const float* Wo = (const float*)d_in[7];
    const float* bo = (const float*)d_in[8];
    float* out = (float*)d_out;

    qkv_kernel<<<dim3(NROWS / 64, 3), 256>>>(x, Wq, bq, Wk, bk, Wv, bv);
    attn_kernel<<<dim3(SEQ / 128, BATCH), 256>>>();
    proj_kernel<<<dim3(NROWS / 64, DMODEL / 64), 256>>>(Wo, bo, out);
}

// round 9
// speedup vs baseline: 5.7449x; 1.9455x over previous
#include <cuda_runtime.h>
#include <cuda_fp16.h>
#include <math.h>
#include <cstdint>

// Fixed problem shapes: B=4, S=4096, D=512, H=64
#define BATCH 4
#define SEQ   4096
#define DMODEL 512
#define DHEAD  64
#define NROWS (BATCH*SEQ)          // 16384

// Scratch (device globals; no allocations allowed).
__device__ __half g_Qh[NROWS*DHEAD];   // fp16 Q row-major [row][h]
__device__ __half g_Kh[NROWS*DHEAD];   // fp16 K row-major
__device__ __half g_Vh[NROWS*DHEAD];   // fp16 V row-major
__device__ __half g_Oh[NROWS*DHEAD];   // fp16 attention output

// ===========================================================================
// Warp-level MMA helpers (portable PTX — compute_103-safe, no tcgen05)
// ===========================================================================
__device__ __forceinline__ uint32_t smem_u32(const void* p) {
    uint32_t a;
    asm("{ .reg .u64 t; cvta.to.shared.u64 t, %1; cvt.u32.u64 %0, t; }" : "=r"(a) : "l"(p));
    return a;
}
// D(16x8,f32) += A(16x16,f16) * B(16x8,f16): row.col
__device__ __forceinline__ void mma16816(float* d, const uint32_t* a, const uint32_t* b) {
    asm volatile(
        "mma.sync.aligned.m16n8k16.row.col.f32.f16.f16.f32 "
        "{%0,%1,%2,%3}, {%4,%5,%6,%7}, {%8,%9}, {%0,%1,%2,%3};"
        : "+f"(d[0]), "+f"(d[1]), "+f"(d[2]), "+f"(d[3])
        : "r"(a[0]), "r"(a[1]), "r"(a[2]), "r"(a[3]), "r"(b[0]), "r"(b[1]));
}
__device__ __forceinline__ void ldsm_x4(uint32_t* r, uint32_t addr) {
    asm volatile("ldmatrix.sync.aligned.m8n8.x4.shared.b16 {%0,%1,%2,%3}, [%4];"
        : "=r"(r[0]), "=r"(r[1]), "=r"(r[2]), "=r"(r[3]) : "r"(addr));
}
__device__ __forceinline__ void ldsm_x2(uint32_t* r, uint32_t addr) {
    asm volatile("ldmatrix.sync.aligned.m8n8.x2.shared.b16 {%0,%1}, [%2];"
        : "=r"(r[0]), "=r"(r[1]) : "r"(addr));
}
__device__ __forceinline__ void ldsm_x2t(uint32_t* r, uint32_t addr) {
    asm volatile("ldmatrix.sync.aligned.m8n8.x2.trans.shared.b16 {%0,%1}, [%2];"
        : "=r"(r[0]), "=r"(r[1]) : "r"(addr));
}
__device__ __forceinline__ float fast_exp2(float x) {
    float r;
    asm("ex2.approx.f32 %0, %1;" : "=f"(r) : "f"(x));
    return r;
}
// pack 8 floats -> 8 halves (uint4)
__device__ __forceinline__ uint4 pack8(float4 a, float4 b) {
    __half2 h0 = __floats2half2_rn(a.x, a.y);
    __half2 h1 = __floats2half2_rn(a.z, a.w);
    __half2 h2 = __floats2half2_rn(b.x, b.y);
    __half2 h3 = __floats2half2_rn(b.z, b.w);
    uint4 u;
    u.x = *(uint32_t*)&h0; u.y = *(uint32_t*)&h1;
    u.z = *(uint32_t*)&h2; u.w = *(uint32_t*)&h3;
    return u;
}

// ===========================================================================
// Kernel 1: QKV projection via mma.sync fp16.
// Block = (128 rows) x (64 cols of one of Q/K/V per blockIdx.y). 8 warps;
// warp w owns rows [16w, 16w+16). K=512 in 8 chunks of 64, register-prefetched.
// Smem swizzle (8-half chunks): chunk (r, c) at r*64 + ((c ^ (r&7))*8).
// ===========================================================================
__global__ __launch_bounds__(256) void qkv_kernel(
    const float* __restrict__ x,
    const float* __restrict__ Wq, const float* __restrict__ bq,
    const float* __restrict__ Wk, const float* __restrict__ bk,
    const float* __restrict__ Wv, const float* __restrict__ bv)
{
    __shared__ __align__(1024) __half Xs[128*64];  // [row][d-chunk] fp16 swizzled
    __shared__ __align__(1024) __half Wc[64*64];   // [d][h] fp16 swizzled

    const int tid  = threadIdx.x;
    const int lane = tid & 31;
    const int warp = tid >> 5;
    const int row0 = blockIdx.x * 128;
    const int g = blockIdx.y;
    const float* W  = (g == 0) ? Wq : (g == 1) ? Wk : Wv;
    const float* bb = (g == 0) ? bq : (g == 1) ? bk : bv;
    __half* dsth    = (g == 0) ? g_Qh : (g == 1) ? g_Kh : g_Vh;

    // ---- load chunk 0 ----
#pragma unroll
    for (int k = 0; k < 4; k++) {
        const int cid = tid + 256 * k;        // 0..1023
        const int r = cid >> 3, c = cid & 7;
        const float* src = &x[(size_t)(row0 + r) * DMODEL + c * 8];
        *(uint4*)&Xs[r * 64 + ((c ^ (r & 7)) * 8)] =
            pack8(*(const float4*)src, *(const float4*)(src + 4));
    }
#pragma unroll
    for (int k = 0; k < 2; k++) {
        const int cid = tid + 256 * k;        // 0..511
        const int r = cid >> 3, c = cid & 7;
        const float* src = &W[(size_t)r * DHEAD + c * 8];
        *(uint4*)&Wc[r * 64 + ((c ^ (r & 7)) * 8)] =
            pack8(*(const float4*)src, *(const float4*)(src + 4));
    }
    __syncthreads();

    const uint32_t xs_b = smem_u32(Xs);
    const uint32_t wc_b = smem_u32(Wc);
    const int rowl = warp * 16 + (lane & 15);
    const int hb   = lane >> 4;
    const int rl   = lane & 7;
    const uint32_t boff = (uint32_t)((lane & 15) * 128);

    float acc[8][4];
#pragma unroll
    for (int j = 0; j < 8; j++)
#pragma unroll
        for (int k = 0; k < 4; k++) acc[j][k] = 0.0f;

    for (int dc8 = 0; dc8 < 8; dc8++) {
        const bool has = (dc8 + 1) < 8;
        uint4 xpre[4], wpre[2];
        if (has) {
            const int dc = (dc8 + 1) * 64;
#pragma unroll
            for (int k = 0; k < 4; k++) {
                const int cid = tid + 256 * k;
                const int r = cid >> 3, c = cid & 7;
                const float* src = &x[(size_t)(row0 + r) * DMODEL + dc + c * 8];
                xpre[k] = pack8(*(const float4*)src, *(const float4*)(src + 4));
            }
#pragma unroll
            for (int k = 0; k < 2; k++) {
                const int cid = tid + 256 * k;
                const int r = cid >> 3, c = cid & 7;
                const float* src = &W[(size_t)(dc + r) * DHEAD + c * 8];
                wpre[k] = pack8(*(const float4*)src, *(const float4*)(src + 4));
            }
        }

        // ---- A fragments for this chunk ----
        uint32_t qa[4][4];
#pragma unroll
        for (int kk = 0; kk < 4; kk++)
            ldsm_x4(qa[kk], xs_b + rowl * 128 + (((2 * kk + hb) ^ (rowl & 7)) * 16));

        // ---- 8 n-frags x 4 k-frags ----
#pragma unroll
        for (int j = 0; j < 8; j++) {
#pragma unroll
            for (int kk = 0; kk < 4; kk++) {
                uint32_t bf[2];
                ldsm_x2t(bf, wc_b + (uint32_t)(kk * 2048) + boff + (uint32_t)(((j ^ rl) * 16)));
                mma16816(acc[j], qa[kk], bf);
            }
        }

        if (has) {
            __syncthreads();
#pragma unroll
            for (int k = 0; k < 4; k++) {
                const int cid = tid + 256 * k;
                const int r = cid >> 3, c = cid & 7;
                *(uint4*)&Xs[r * 64 + ((c ^ (r & 7)) * 8)] = xpre[k];
            }
#pragma unroll
            for (int k = 0; k < 2; k++) {
                const int cid = tid + 256 * k;
                const int r = cid >> 3, c = cid & 7;
                *(uint4*)&Wc[r * 64 + ((c ^ (r & 7)) * 8)] = wpre[k];
            }
            __syncthreads();
        }
    }

    // ---- epilogue: + bias, fp16 store ----
    const int r0 = row0 + warp * 16 + (lane >> 2);
    const int cb = 2 * (lane & 3);
#pragma unroll
    for (int j = 0; j < 8; j++) {
        const int c = 8 * j + cb;
        const float bx = bb[c], by = bb[c + 1];
        __half2 h0 = __floats2half2_rn(acc[j][0] + bx, acc[j][1] + by);
        __half2 h1 = __floats2half2_rn(acc[j][2] + bx, acc[j][3] + by);
        *(__half2*)&dsth[(size_t)r0 * DHEAD + c]       = h0;
        *(__half2*)&dsth[(size_t)(r0 + 8) * DHEAD + c] = h1;
    }
}

// ===========================================================================
// Kernel 2: fp16 mma.sync flash attention (FA2-style) with K/V reg-prefetch.
// One block = (q-tile of 128, batch). 8 warps; warp w owns q-rows [16w,16w+16).
// ===========================================================================
__global__ __launch_bounds__(256, 1) void attn_kernel()
{
    __shared__ __align__(1024) __half Qs[128*64];
    __shared__ __align__(1024) __half Ks[64*64];
    __shared__ __align__(1024) __half Vs[64*64];

    const int tid  = threadIdx.x;
    const int lane = tid & 31;
    const int warp = tid >> 5;
    const int qt = blockIdx.x;           // 0..31
    const int b  = blockIdx.y;           // 0..3
    const int qbase = qt * 128;

    // load Q tile + K/V tile 0
    const __half* Qg = g_Qh + ((size_t)b * SEQ + qbase) * DHEAD;
    for (int i = tid; i < 1024; i += 256) {
        const int r = i >> 3, c = i & 7;
        uint4 v = *(const uint4*)&Qg[(size_t)r * 64 + c * 8];
        *(uint4*)&Qs[r * 64 + ((c ^ (r & 7)) * 8)] = v;
    }
    {
        const __half* Kg = g_Kh + (size_t)b * SEQ * DHEAD;
        const __half* Vg = g_Vh + (size_t)b * SEQ * DHEAD;
        for (int i = tid; i < 512; i += 256) {
            const int r = i >> 3, c = i & 7;
            *(uint4*)&Ks[r * 64 + ((c ^ (r & 7)) * 8)] = *(const uint4*)&Kg[(size_t)r * 64 + c * 8];
            *(uint4*)&Vs[r * 64 + ((c ^ (r & 7)) * 8)] = *(const uint4*)&Vg[(size_t)r * 64 + c * 8];
        }
    }
    __syncthreads();

    const uint32_t qs_b = smem_u32(Qs);
    const uint32_t ks_b = smem_u32(Ks);
    const uint32_t vs_b = smem_u32(Vs);

    // persistent Q A-fragments
    const int q0 = warp * 16;
    uint32_t qa[4][4];
    {
        const int rowl = q0 + (lane & 15);
        const int hb = lane >> 4;
#pragma unroll
        for (int kk = 0; kk < 4; kk++)
            ldsm_x4(qa[kk], qs_b + rowl * 128 + (((2 * kk + hb) ^ (rowl & 7)) * 16));
    }

    const int rl  = lane & 7;
    const int hb8 = (lane >> 3) & 1;
    uint32_t koff[4];
#pragma unroll
    for (int kk = 0; kk < 4; kk++)
        koff[kk] = (uint32_t)(rl * 128 + (((2 * kk + hb8) ^ rl) * 16));
    const uint32_t voff = (uint32_t)((lane & 15) * 128);

    const int row0 = qbase + q0 + (lane >> 2);
    const float C = 0.015625f * 1.44269504088896f; // (1/sqrt(4096)) * log2(e)

    float m0 = -1e30f, m1 = -1e30f, l0 = 0.0f, l1 = 0.0f;
    float o[8][4];
#pragma unroll
    for (int j = 0; j < 8; j++)
#pragma unroll
        for (int k = 0; k < 4; k++) o[j][k] = 0.0f;

    const int nkb = 2 * qt + 2;

    for (int kb = 0; kb < nkb; kb++) {
        // ---- prefetch next K/V tile into registers ----
        const bool has = (kb + 1) < nkb;
        uint4 kpre[2], vpre[2];
        if (has) {
            const __half* Kg = g_Kh + ((size_t)b * SEQ + (kb + 1) * 64) * DHEAD;
            const __half* Vg = g_Vh + ((size_t)b * SEQ + (kb + 1) * 64) * DHEAD;
#pragma unroll
            for (int t = 0; t < 2; t++) {
                const int i = tid + 256 * t;
                const int r = i >> 3, c = i & 7;
                kpre[t] = *(const uint4*)&Kg[(size_t)r * 64 + c * 8];
                vpre[t] = *(const uint4*)&Vg[(size_t)r * 64 + c * 8];
            }
        }

        // ---- S = Q * K^T ----
        float s[8][4];
#pragma unroll
        for (int j = 0; j < 8; j++)
#pragma unroll
            for (int k = 0; k < 4; k++) s[j][k] = 0.0f;

#pragma unroll
        for (int j = 0; j < 8; j++) {
#pragma unroll
            for (int kk = 0; kk < 4; kk++) {
                uint32_t bf[2];
                ldsm_x2(bf, ks_b + (uint32_t)(j * 1024) + koff[kk]);
                mma16816(s[j], qa[kk], bf);
            }
        }

        // ---- scale (+ causal mask on diagonal tiles) ----
#pragma unroll
        for (int j = 0; j < 8; j++)
#pragma unroll
            for (int k = 0; k < 4; k++) s[j][k] *= C;

        if (kb * 64 + 63 > qbase + q0) {
#pragma unroll
            for (int j = 0; j < 8; j++) {
                const int kc = kb * 64 + 8 * j + 2 * (lane & 3);
                if (kc     > row0)     s[j][0] = -1e30f;
                if (kc + 1 > row0)     s[j][1] = -1e30f;
                if (kc     > row0 + 8) s[j][2] = -1e30f;
                if (kc + 1 > row0 + 8) s[j][3] = -1e30f;
            }
        }

        // ---- online softmax ----
        float mx0 = -1e30f, mx1 = -1e30f;
#pragma unroll
        for (int j = 0; j < 8; j++) {
            mx0 = fmaxf(mx0, fmaxf(s[j][0], s[j][1]));
            mx1 = fmaxf(mx1, fmaxf(s[j][2], s[j][3]));
        }
        mx0 = fmaxf(mx0, __shfl_xor_sync(0xffffffffu, mx0, 1, 4));
        mx0 = fmaxf(mx0, __shfl_xor_sync(0xffffffffu, mx0, 2, 4));
        mx1 = fmaxf(mx1, __shfl_xor_sync(0xffffffffu, mx1, 1, 4));
        mx1 = fmaxf(mx1, __shfl_xor_sync(0xffffffffu, mx1, 2, 4));

        const float mn0 = fmaxf(m0, mx0);
        const float mn1 = fmaxf(m1, mx1);
        const float c0 = fast_exp2(m0 - mn0);
        const float c1 = fast_exp2(m1 - mn1);
        m0 = mn0; m1 = mn1;

        uint32_t pa[4][4];
        float sum0 = 0.0f, sum1 = 0.0f;
#pragma unroll
        for (int j = 0; j < 8; j++) {
            const float p0 = fast_exp2(s[j][0] - mn0);
            const float p1 = fast_exp2(s[j][1] - mn0);
            const float p2 = fast_exp2(s[j][2] - mn1);
            const float p3 = fast_exp2(s[j][3] - mn1);
            sum0 += p0 + p1;
            sum1 += p2 + p3;
            const __half2 h01 = __floats2half2_rn(p0, p1);
            const __half2 h23 = __floats2half2_rn(p2, p3);
            const int kk = j >> 1, hi = (j & 1) << 1;
            pa[kk][hi]     = *(const uint32_t*)&h01;
            pa[kk][hi + 1] = *(const uint32_t*)&h23;
        }
        sum0 += __shfl_xor_sync(0xffffffffu, sum0, 1, 4);
        sum0 += __shfl_xor_sync(0xffffffffu, sum0, 2, 4);
        sum1 += __shfl_xor_sync(0xffffffffu, sum1, 1, 4);
        sum1 += __shfl_xor_sync(0xffffffffu, sum1, 2, 4);
        l0 = l0 * c0 + sum0;
        l1 = l1 * c1 + sum1;

#pragma unroll
        for (int j = 0; j < 8; j++) {
            o[j][0] *= c0; o[j][1] *= c0;
            o[j][2] *= c1; o[j][3] *= c1;
        }

        // ---- O += P * V ----
#pragma unroll
        for (int kk = 0; kk < 4; kk++) {
#pragma unroll
            for (int j = 0; j < 8; j++) {
                uint32_t vb[2];
                ldsm_x2t(vb, vs_b + (uint32_t)(kk * 2048) + voff + (uint32_t)(((j ^ rl) * 16)));
                mma16816(o[j], pa[kk], vb);
            }
        }

        if (has) {
            __syncthreads();
#pragma unroll
            for (int t = 0; t < 2; t++) {
                const int i = tid + 256 * t;
                const int r = i >> 3, c = i & 7;
                *(uint4*)&Ks[r * 64 + ((c ^ (r & 7)) * 8)] = kpre[t];
                *(uint4*)&Vs[r * 64 + ((c ^ (r & 7)) * 8)] = vpre[t];
            }
            __syncthreads();
        }
    }

    // ---- epilogue: fp16 O rows ----
    const float inv0 = 1.0f / l0;
    const float inv1 = 1.0f / l1;
    __half* O0 = g_Oh + ((size_t)b * SEQ + row0) * DHEAD;
    __half* O1 = O0 + 8 * DHEAD;
    const int cbase = 2 * (lane & 3);
#pragma unroll
    for (int j = 0; j < 8; j++) {
        __half2 w0 = __floats2half2_rn(o[j][0] * inv0, o[j][1] * inv0);
        __half2 w1 = __floats2half2_rn(o[j][2] * inv1, o[j][3] * inv1);
        *(__half2*)&O0[8 * j + cbase] = w0;
        *(__half2*)&O1[8 * j + cbase] = w1;
    }
}

// ===========================================================================
// Kernel 3: output projection via mma.sync fp16. Block = 128 rows x 128 cols,
// K=64 (single chunk). 8 warps; warp w owns rows [16w, 16w+16).
// Wo tile split into two 64-col smem regions (validated 128B-row layout).
// ===========================================================================
__global__ __launch_bounds__(256) void proj_kernel(
    const float* __restrict__ Wo, const float* __restrict__ bo,
    float* __restrict__ out)
{
    __shared__ __align__(1024) __half Os[128*64];
    __shared__ __align__(1024) __half Wc0[64*64];
    __shared__ __align__(1024) __half Wc1[64*64];

    const int tid  = threadIdx.x;
    const int lane = tid & 31;
    const int warp = tid >> 5;
    const int row0 = blockIdx.x * 128;
    const int c0   = blockIdx.y * 128;

    // O tile (fp16, direct)
    for (int i = tid; i < 1024; i += 256) {
        const int r = i >> 3, c = i & 7;
        *(uint4*)&Os[r * 64 + ((c ^ (r & 7)) * 8)] =
            *(const uint4*)&g_Oh[(size_t)(row0 + r) * DHEAD + c * 8];
    }
    // Wo tile: rows h 0..63, cols c0..c0+128 (fp32 -> fp16)
    for (int i = tid; i < 1024; i += 256) {
        const int h = i >> 4, c = i & 15;
        const float* src = &Wo[(size_t)h * DMODEL + c0 + c * 8];
        uint4 u = pack8(*(const float4*)src, *(const float4*)(src + 4));
        __half* dst = (c < 8) ? Wc0 : Wc1;
        const int cc = c & 7;
        *(uint4*)&dst[h * 64 + ((cc ^ (h & 7)) * 8)] = u;
    }
    __syncthreads();

    const uint32_t os_b  = smem_u32(Os);
    const uint32_t wc0_b = smem_u32(Wc0);
    const uint32_t wc1_b = smem_u32(Wc1);

    // A fragments
    const int rowl = warp * 16 + (lane & 15);
    const int hb = lane >> 4;
    uint32_t qa[4][4];
#pragma unroll
    for (int kk = 0; kk < 4; kk++)
        ldsm_x4(qa[kk], os_b + rowl * 128 + (((2 * kk + hb) ^ (rowl & 7)) * 16));

    const int rl = lane & 7;
    const uint32_t boff = (uint32_t)((lane & 15) * 128);

    float acc[16][4];
#pragma unroll
    for (int j = 0; j < 16; j++)
#pragma unroll
        for (int k = 0; k < 4; k++) acc[j][k] = 0.0f;

#pragma unroll
    for (int j = 0; j < 16; j++) {
        const uint32_t base = (j < 8) ? wc0_b : wc1_b;
        const int jj = j & 7;
#pragma unroll
        for (int kk = 0; kk < 4; kk++) {
            uint32_t bf[2];
            ldsm_x2t(bf, base + (uint32_t)(kk * 2048) + boff + (uint32_t)(((jj ^ rl) * 16)));
            mma16816(acc[j], qa[kk], bf);
        }
    }

    // epilogue: + bias, fp32 out
    const int r0 = row0 + warp * 16 + (lane >> 2);
    const int cb = 2 * (lane & 3);
#pragma unroll
    for (int j = 0; j < 16; j++) {
        const int c = c0 + 8 * j + cb;
        const float bx = bo[c], by = bo[c + 1];
        float2 w0 = make_float2(acc[j][0] + bx, acc[j][1] + by);
        float2 w1 = make_float2(acc[j][2] + bx, acc[j][3] + by);
        *(float2*)&out[(size_t)r0 * DMODEL + c]       = w0;
        *(float2*)&out[(size_t)(r0 + 8) * DMODEL + c] = w1;
    }
}

// ---------------------------------------------------------------------------
extern "C" void kernel_launch(void* const* d_in, const int* in_sizes, int n_in,
                              void* d_out, int out_size)
{
    const float* x  = (const float*)d_in[0];
    const float* Wq = (const float*)d_in[1];
    const float* bq = (const float*)d_in[2];
    const float* Wk = (const float*)d_in[3];
    const float* bk = (const float*)d_in[4];
    const float* Wv = (const float*)d_in[5];
    const float* bv = (const float*)d_in[6];
    const float* Wo = (const float*)d_in[7];
    const float* bo = (const float*)d_in[8];
    float* out = (float*)d_out;

    qkv_kernel<<<dim3(NROWS / 128, 3), 256>>>(x, Wq, bq, Wk, bk, Wv, bv);
    attn_kernel<<<dim3(SEQ / 128, BATCH), 256>>>();
    proj_kernel<<<dim3(NROWS / 128, DMODEL / 128), 256>>>(Wo, bo, out);
}